// round 3
// baseline (speedup 1.0000x reference)
#include <cuda_runtime.h>
#include <cstdint>

// ---------------------------------------------------------------------------
// MultiHeadedEMA: the reference FFT conv == causal/anti-causal first-order EMA.
//   fwd: y[t] = q*y[t-1] + a*x[t]   (per head h, per channel d)
//   rev: y[t] = q*y[t+1] + a*x[t]
// expansion factors out of the linear scan and fuses with reduction:
//   out[b,l,d] = sum_h wf[h,d]*uf_h[b,l,d] + wr[h,d]*ur_h[b,l,d]
//   with u = q*u + x (a folded into w = expansion*reduction*a).
// 3-kernel chunked scan to parallelize over L.
// ---------------------------------------------------------------------------

constexpr int kB = 2;
constexpr int kL = 2048;
constexpr int kD = 1024;
constexpr int kH = 8;

constexpr int kChunk   = 16;
constexpr int kNChunk  = kL / kChunk;       // 128
constexpr int kCols    = 256;               // d-columns per block
constexpr int kThreads = 128;               // 2 columns per thread (f32x2)
constexpr int kDTiles  = kD / kCols;        // 4
constexpr int kBlocks  = kB * kNChunk * kDTiles;  // 1024

// Scratch: per-chunk end states and incoming prefixes, fwd and rev.
__device__ __align__(16) float g_sf[kB][kNChunk][kH][kD];
__device__ __align__(16) float g_sr[kB][kNChunk][kH][kD];
__device__ __align__(16) float g_pf[kB][kNChunk][kH][kD];
__device__ __align__(16) float g_pr[kB][kNChunk][kH][kD];

using u64 = unsigned long long;

__device__ __forceinline__ u64 pack2(float lo, float hi) {
    u64 r;
    asm("mov.b64 %0, {%1, %2};"
        : "=l"(r) : "r"(__float_as_uint(lo)), "r"(__float_as_uint(hi)));
    return r;
}
__device__ __forceinline__ u64 fma2(u64 a, u64 b, u64 c) {
    u64 r;
    asm("fma.rn.f32x2 %0, %1, %2, %3;" : "=l"(r) : "l"(a), "l"(b), "l"(c));
    return r;
}
__device__ __forceinline__ u64 add2(u64 a, u64 b) {
    u64 r;
    asm("add.rn.f32x2 %0, %1, %2;" : "=l"(r) : "l"(a), "l"(b));
    return r;
}

__device__ __forceinline__ float sigd(float v) {
    // double-precision sigmoid so q is accurate to fp32 ulp (q^L amplifies error)
    return (float)(1.0 / (1.0 + exp(-(double)v)));
}

// ---------------------------------------------------------------------------
// Phase 1: per-chunk local scans (zero-init), store end states.
// ---------------------------------------------------------------------------
__global__ void __launch_bounds__(kThreads)
ema_phase1(const float* __restrict__ x,
           const float* __restrict__ al,  const float* __restrict__ da,
           const float* __restrict__ ral, const float* __restrict__ rda)
{
    const int tid = threadIdx.x;
    const int blk = blockIdx.x;
    const int dt = blk & (kDTiles - 1);
    const int c  = (blk >> 2) & (kNChunk - 1);
    const int b  = blk >> 9;

    const u64* xs = reinterpret_cast<const u64*>(
        x + ((size_t)b * kL + (size_t)c * kChunk) * kD + dt * kCols) + tid;

    u64 q2f[kH], q2r[kH];
#pragma unroll
    for (int h = 0; h < kH; ++h) {
        float a  = sigd(al[h]);
        float qf = (1.0f - a) * sigd(da[h]);
        float ar = sigd(ral[h]);
        float qr = (1.0f - ar) * sigd(rda[h]);
        q2f[h] = pack2(qf, qf);
        q2r[h] = pack2(qr, qr);
    }

    const int d = dt * kCols + 2 * tid;

    u64 s[kH];
#pragma unroll
    for (int h = 0; h < kH; ++h) s[h] = 0ull;
#pragma unroll
    for (int i = 0; i < kChunk; ++i) {
        u64 xv = xs[i * (kD / 2)];
#pragma unroll
        for (int h = 0; h < kH; ++h) s[h] = fma2(q2f[h], s[h], xv);
    }
#pragma unroll
    for (int h = 0; h < kH; ++h)
        *reinterpret_cast<u64*>(&g_sf[b][c][h][d]) = s[h];

#pragma unroll
    for (int h = 0; h < kH; ++h) s[h] = 0ull;
#pragma unroll
    for (int i = kChunk - 1; i >= 0; --i) {
        u64 xv = xs[i * (kD / 2)];
#pragma unroll
        for (int h = 0; h < kH; ++h) s[h] = fma2(q2r[h], s[h], xv);
    }
#pragma unroll
    for (int h = 0; h < kH; ++h)
        *reinterpret_cast<u64*>(&g_sr[b][c][h][d]) = s[h];
}

// ---------------------------------------------------------------------------
// Phase 2: chain chunk states across chunks with q^kChunk; emit per-chunk
// incoming prefixes. One thread per (b, dir, h, d).
// ---------------------------------------------------------------------------
__global__ void ema_phase2(const float* __restrict__ al,  const float* __restrict__ da,
                           const float* __restrict__ ral, const float* __restrict__ rda)
{
    const int t = blockIdx.x * blockDim.x + threadIdx.x;   // 32768 total
    const int d   = t & (kD - 1);
    const int h   = (t >> 10) & (kH - 1);
    const int rev = (t >> 13) & 1;
    const int b   = t >> 14;

    float a, dd;
    if (rev) { a = sigd(ral[h]); dd = sigd(rda[h]); }
    else     { a = sigd(al[h]);  dd = sigd(da[h]);  }
    float qc = (1.0f - a) * dd;
#pragma unroll
    for (int k = 0; k < 4; ++k) qc *= qc;   // q^16 (kChunk = 16)

    const int stride = kH * kD;
    const float* st = rev ? &g_sr[b][0][h][d] : &g_sf[b][0][h][d];
    float*       pr = rev ? &g_pr[b][0][h][d] : &g_pf[b][0][h][d];

    float p = 0.0f;
    if (!rev) {
        for (int c = 0; c < kNChunk; ++c) {
            pr[(size_t)c * stride] = p;
            p = fmaf(qc, p, st[(size_t)c * stride]);
        }
    } else {
        for (int c = kNChunk - 1; c >= 0; --c) {
            pr[(size_t)c * stride] = p;
            p = fmaf(qc, p, st[(size_t)c * stride]);
        }
    }
}

// ---------------------------------------------------------------------------
// Phase 3: rescan each chunk seeded with its prefix; apply fused weights
// w = expansion*reduction*a; out = fwd + rev, written once.
// ---------------------------------------------------------------------------
__global__ void __launch_bounds__(kThreads)
ema_phase3(const float* __restrict__ x,
           const float* __restrict__ ex,  const float* __restrict__ re,
           const float* __restrict__ al,  const float* __restrict__ da,
           const float* __restrict__ ral, const float* __restrict__ rda,
           float* __restrict__ out)
{
    __shared__ u64 acc[kChunk * kThreads];   // 16 KB, per-thread private slots

    const int tid = threadIdx.x;
    const int blk = blockIdx.x;
    const int dt = blk & (kDTiles - 1);
    const int c  = (blk >> 2) & (kNChunk - 1);
    const int b  = blk >> 9;

    const u64* xs = reinterpret_cast<const u64*>(
        x + ((size_t)b * kL + (size_t)c * kChunk) * kD + dt * kCols) + tid;
    const int d = dt * kCols + 2 * tid;

    u64 q2f[kH], q2r[kH], wf[kH], wr[kH];
#pragma unroll
    for (int h = 0; h < kH; ++h) {
        float a  = sigd(al[h]);
        float qf = (1.0f - a) * sigd(da[h]);
        float ar = sigd(ral[h]);
        float qr = (1.0f - ar) * sigd(rda[h]);
        q2f[h] = pack2(qf, qf);
        q2r[h] = pack2(qr, qr);
        float e0 = ex[h * kD + d],     e1 = ex[h * kD + d + 1];
        float r0 = re[h * kD + d],     r1 = re[h * kD + d + 1];
        wf[h] = pack2(e0 * r0 * a, e1 * r1 * a);
        e0 = ex[(kH + h) * kD + d];    e1 = ex[(kH + h) * kD + d + 1];
        r0 = re[(kH + h) * kD + d];    r1 = re[(kH + h) * kD + d + 1];
        wr[h] = pack2(e0 * r0 * ar, e1 * r1 * ar);
    }

    u64 u[kH];
#pragma unroll
    for (int h = 0; h < kH; ++h)
        u[h] = *reinterpret_cast<const u64*>(&g_pf[b][c][h][d]);

#pragma unroll
    for (int i = 0; i < kChunk; ++i) {
        u64 xv = xs[i * (kD / 2)];
        u64 fs = 0ull;
#pragma unroll
        for (int h = 0; h < kH; ++h) {
            u[h] = fma2(q2f[h], u[h], xv);
            fs   = fma2(wf[h], u[h], fs);
        }
        acc[i * kThreads + tid] = fs;
    }

#pragma unroll
    for (int h = 0; h < kH; ++h)
        u[h] = *reinterpret_cast<const u64*>(&g_pr[b][c][h][d]);

    u64* od = reinterpret_cast<u64*>(
        out + ((size_t)b * kL + (size_t)c * kChunk) * kD + dt * kCols) + tid;

#pragma unroll
    for (int i = kChunk - 1; i >= 0; --i) {
        u64 xv = xs[i * (kD / 2)];   // L1-hot re-read
        u64 rs = 0ull;
#pragma unroll
        for (int h = 0; h < kH; ++h) {
            u[h] = fma2(q2r[h], u[h], xv);
            rs   = fma2(wr[h], u[h], rs);
        }
        od[i * (kD / 2)] = add2(acc[i * kThreads + tid], rs);
    }
}

// ---------------------------------------------------------------------------
extern "C" void kernel_launch(void* const* d_in, const int* in_sizes, int n_in,
                              void* d_out, int out_size)
{
    const float* x   = (const float*)d_in[0];
    const float* ex  = (const float*)d_in[1];
    const float* re  = (const float*)d_in[2];
    const float* al  = (const float*)d_in[3];
    const float* da  = (const float*)d_in[4];
    const float* ral = (const float*)d_in[5];
    const float* rda = (const float*)d_in[6];
    float* out = (float*)d_out;

    ema_phase1<<<kBlocks, kThreads>>>(x, al, da, ral, rda);
    ema_phase2<<<(kB * 2 * kH * kD) / 256, 256>>>(al, da, ral, rda);
    ema_phase3<<<kBlocks, kThreads>>>(x, ex, re, al, da, ral, rda, out);
}

// round 4
// speedup vs baseline: 9.1579x; 9.1579x over previous
#include <cuda_runtime.h>
#include <cstdint>

// ---------------------------------------------------------------------------
// MultiHeadedEMA == causal + anti-causal first-order EMA per (head, channel).
//   fwd: u[t] = q*u[t-1] + x[t] ;  rev: u[t] = q*u[t+1] + x[t]
//   out[b,l,d] = sum_h wf[h,d]*uf + wr[h,d]*ur,  w = expansion*reduction*a
// 3-phase chunked scan. Round-3 fix: all double-precision sigmoids moved to a
// one-warp setup kernel (fp64 exp was 95% of runtime); scan phases are pure
// packed f32x2 FMA + coalesced memory.
// ---------------------------------------------------------------------------

constexpr int kB = 2;
constexpr int kL = 2048;
constexpr int kD = 1024;
constexpr int kH = 8;

constexpr int kChunk   = 16;
constexpr int kNChunk  = kL / kChunk;       // 128
constexpr int kCols    = 256;               // d-columns per block
constexpr int kThreads = 128;               // 2 cols/thread -> f32x2
constexpr int kDTiles  = kD / kCols;        // 4
constexpr int kBlocks  = kB * kNChunk * kDTiles;  // 1024

// Scratch: per-chunk end states / incoming prefixes, fwd and rev.
__device__ __align__(16) float g_sf[kB][kNChunk][kH][kD];
__device__ __align__(16) float g_sr[kB][kNChunk][kH][kD];
__device__ __align__(16) float g_pf[kB][kNChunk][kH][kD];
__device__ __align__(16) float g_pr[kB][kNChunk][kH][kD];

// Precomputed per-head constants (written by ema_setup).
__device__ float g_qf[kH], g_qr[kH];     // decay q
__device__ float g_af[kH], g_ar[kH];     // sigmoid(alpha)
__device__ float g_qcf[kH], g_qcr[kH];   // q^kChunk

using u64 = unsigned long long;

__device__ __forceinline__ u64 pack2(float lo, float hi) {
    u64 r;
    asm("mov.b64 %0, {%1, %2};"
        : "=l"(r) : "r"(__float_as_uint(lo)), "r"(__float_as_uint(hi)));
    return r;
}
__device__ __forceinline__ u64 fma2(u64 a, u64 b, u64 c) {
    u64 r;
    asm("fma.rn.f32x2 %0, %1, %2, %3;" : "=l"(r) : "l"(a), "l"(b), "l"(c));
    return r;
}
__device__ __forceinline__ u64 add2(u64 a, u64 b) {
    u64 r;
    asm("add.rn.f32x2 %0, %1, %2;" : "=l"(r) : "l"(a), "l"(b));
    return r;
}

// ---------------------------------------------------------------------------
// Setup: one warp does all the fp64 sigmoids ONCE.
// ---------------------------------------------------------------------------
__global__ void ema_setup(const float* __restrict__ al,  const float* __restrict__ da,
                          const float* __restrict__ ral, const float* __restrict__ rda)
{
    const int h = threadIdx.x;
    if (h >= kH) return;

    double a = 1.0 / (1.0 + exp(-(double)al[h]));
    double q = (1.0 - a) * (1.0 / (1.0 + exp(-(double)da[h])));
    g_af[h] = (float)a;
    g_qf[h] = (float)q;
    double qc = q;
#pragma unroll
    for (int k = 0; k < 4; ++k) qc *= qc;      // q^16
    g_qcf[h] = (float)qc;

    a = 1.0 / (1.0 + exp(-(double)ral[h]));
    q = (1.0 - a) * (1.0 / (1.0 + exp(-(double)rda[h])));
    g_ar[h] = (float)a;
    g_qr[h] = (float)q;
    qc = q;
#pragma unroll
    for (int k = 0; k < 4; ++k) qc *= qc;
    g_qcr[h] = (float)qc;
}

// ---------------------------------------------------------------------------
// Phase 1: per-chunk local scans (zero-init), store end states.
// x rows of the chunk are cached in registers (single global read).
// ---------------------------------------------------------------------------
__global__ void __launch_bounds__(kThreads)
ema_phase1(const float* __restrict__ x)
{
    const int tid = threadIdx.x;
    const int blk = blockIdx.x;
    const int dt = blk & (kDTiles - 1);
    const int c  = (blk >> 2) & (kNChunk - 1);
    const int b  = blk >> 9;

    const u64* xs = reinterpret_cast<const u64*>(
        x + ((size_t)b * kL + (size_t)c * kChunk) * kD + dt * kCols) + tid;

    u64 xv[kChunk];
#pragma unroll
    for (int i = 0; i < kChunk; ++i) xv[i] = xs[i * (kD / 2)];

    u64 q2f[kH], q2r[kH];
#pragma unroll
    for (int h = 0; h < kH; ++h) {
        float qf = g_qf[h], qr = g_qr[h];
        q2f[h] = pack2(qf, qf);
        q2r[h] = pack2(qr, qr);
    }

    const int d = dt * kCols + 2 * tid;

    u64 s[kH];
#pragma unroll
    for (int h = 0; h < kH; ++h) s[h] = 0ull;
#pragma unroll
    for (int i = 0; i < kChunk; ++i)
#pragma unroll
        for (int h = 0; h < kH; ++h) s[h] = fma2(q2f[h], s[h], xv[i]);
#pragma unroll
    for (int h = 0; h < kH; ++h)
        *reinterpret_cast<u64*>(&g_sf[b][c][h][d]) = s[h];

#pragma unroll
    for (int h = 0; h < kH; ++h) s[h] = 0ull;
#pragma unroll
    for (int i = kChunk - 1; i >= 0; --i)
#pragma unroll
        for (int h = 0; h < kH; ++h) s[h] = fma2(q2r[h], s[h], xv[i]);
#pragma unroll
    for (int h = 0; h < kH; ++h)
        *reinterpret_cast<u64*>(&g_sr[b][c][h][d]) = s[h];
}

// ---------------------------------------------------------------------------
// Phase 2: chain chunk states with q^kChunk; emit per-chunk incoming prefixes.
// One thread per (b, dir, h, d).
// ---------------------------------------------------------------------------
__global__ void ema_phase2()
{
    const int t = blockIdx.x * blockDim.x + threadIdx.x;   // 32768 total
    const int d   = t & (kD - 1);
    const int h   = (t >> 10) & (kH - 1);
    const int rev = (t >> 13) & 1;
    const int b   = t >> 14;

    const float qc = rev ? g_qcr[h] : g_qcf[h];
    const int stride = kH * kD;
    const float* st = rev ? &g_sr[b][0][h][d] : &g_sf[b][0][h][d];
    float*       pr = rev ? &g_pr[b][0][h][d] : &g_pf[b][0][h][d];

    float p = 0.0f;
    if (!rev) {
        for (int c = 0; c < kNChunk; ++c) {
            pr[(size_t)c * stride] = p;
            p = fmaf(qc, p, st[(size_t)c * stride]);
        }
    } else {
        for (int c = kNChunk - 1; c >= 0; --c) {
            pr[(size_t)c * stride] = p;
            p = fmaf(qc, p, st[(size_t)c * stride]);
        }
    }
}

// ---------------------------------------------------------------------------
// Phase 3: rescan each chunk seeded with its prefix; apply fused weights
// w = expansion*reduction*a; out = fwd + rev, written once.
// ---------------------------------------------------------------------------
__global__ void __launch_bounds__(kThreads)
ema_phase3(const float* __restrict__ x,
           const float* __restrict__ ex,  const float* __restrict__ re,
           float* __restrict__ out)
{
    __shared__ u64 acc[kChunk * kThreads];   // 16 KB, per-thread private slots

    const int tid = threadIdx.x;
    const int blk = blockIdx.x;
    const int dt = blk & (kDTiles - 1);
    const int c  = (blk >> 2) & (kNChunk - 1);
    const int b  = blk >> 9;

    const u64* xs = reinterpret_cast<const u64*>(
        x + ((size_t)b * kL + (size_t)c * kChunk) * kD + dt * kCols) + tid;
    const int d = dt * kCols + 2 * tid;

    u64 xv[kChunk];
#pragma unroll
    for (int i = 0; i < kChunk; ++i) xv[i] = xs[i * (kD / 2)];

    u64 q2f[kH], q2r[kH], wf[kH], wr[kH];
#pragma unroll
    for (int h = 0; h < kH; ++h) {
        float qf = g_qf[h], qr = g_qr[h];
        float a  = g_af[h], ar = g_ar[h];
        q2f[h] = pack2(qf, qf);
        q2r[h] = pack2(qr, qr);
        float e0 = ex[h * kD + d],  e1 = ex[h * kD + d + 1];
        float r0 = re[h * kD + d],  r1 = re[h * kD + d + 1];
        wf[h] = pack2(e0 * r0 * a, e1 * r1 * a);
        e0 = ex[(kH + h) * kD + d]; e1 = ex[(kH + h) * kD + d + 1];
        r0 = re[(kH + h) * kD + d]; r1 = re[(kH + h) * kD + d + 1];
        wr[h] = pack2(e0 * r0 * ar, e1 * r1 * ar);
    }

    u64 u[kH];
#pragma unroll
    for (int h = 0; h < kH; ++h)
        u[h] = *reinterpret_cast<const u64*>(&g_pf[b][c][h][d]);

#pragma unroll
    for (int i = 0; i < kChunk; ++i) {
        u64 fs = 0ull;
#pragma unroll
        for (int h = 0; h < kH; ++h) {
            u[h] = fma2(q2f[h], u[h], xv[i]);
            fs   = fma2(wf[h], u[h], fs);
        }
        acc[i * kThreads + tid] = fs;
    }

#pragma unroll
    for (int h = 0; h < kH; ++h)
        u[h] = *reinterpret_cast<const u64*>(&g_pr[b][c][h][d]);

    u64* od = reinterpret_cast<u64*>(
        out + ((size_t)b * kL + (size_t)c * kChunk) * kD + dt * kCols) + tid;

#pragma unroll
    for (int i = kChunk - 1; i >= 0; --i) {
        u64 rs = 0ull;
#pragma unroll
        for (int h = 0; h < kH; ++h) {
            u[h] = fma2(q2r[h], u[h], xv[i]);
            rs   = fma2(wr[h], u[h], rs);
        }
        od[i * (kD / 2)] = add2(acc[i * kThreads + tid], rs);
    }
}

// ---------------------------------------------------------------------------
extern "C" void kernel_launch(void* const* d_in, const int* in_sizes, int n_in,
                              void* d_out, int out_size)
{
    const float* x   = (const float*)d_in[0];
    const float* ex  = (const float*)d_in[1];
    const float* re  = (const float*)d_in[2];
    const float* al  = (const float*)d_in[3];
    const float* da  = (const float*)d_in[4];
    const float* ral = (const float*)d_in[5];
    const float* rda = (const float*)d_in[6];
    float* out = (float*)d_out;

    ema_setup<<<1, 32>>>(al, da, ral, rda);
    ema_phase1<<<kBlocks, kThreads>>>(x);
    ema_phase2<<<(kB * 2 * kH * kD) / 256, 256>>>();
    ema_phase3<<<kBlocks, kThreads>>>(x, ex, re, out);
}

// round 5
// speedup vs baseline: 9.3422x; 1.0201x over previous
#include <cuda_runtime.h>
#include <cstdint>

// ---------------------------------------------------------------------------
// MultiHeadedEMA == causal + anti-causal first-order EMA per (head, channel).
//   fwd: u[t] = q*u[t-1] + x[t] ;  rev: u[t] = q*u[t+1] + x[t]
//   out[b,l,d] = sum_h wf[h,d]*uf + wr[h,d]*ur,  w = expansion*reduction*a
// 3-phase chunked scan. Round-4 changes: fp32 per-block constants (setup
// kernel removed), chunk x cached in SMEM not registers (occupancy),
// streaming stores for out (L2 keeps x hot for the phase-3 re-read).
// ---------------------------------------------------------------------------

constexpr int kB = 2;
constexpr int kL = 2048;
constexpr int kD = 1024;
constexpr int kH = 8;

constexpr int kChunk   = 16;
constexpr int kNChunk  = kL / kChunk;       // 128
constexpr int kCols    = 256;               // d-columns per block
constexpr int kThreads = 128;               // 2 cols/thread -> f32x2
constexpr int kDTiles  = kD / kCols;        // 4
constexpr int kBlocks  = kB * kNChunk * kDTiles;  // 1024

// Scratch: per-chunk end states / incoming prefixes, fwd and rev. (32 MB, L2)
__device__ __align__(16) float g_sf[kB][kNChunk][kH][kD];
__device__ __align__(16) float g_sr[kB][kNChunk][kH][kD];
__device__ __align__(16) float g_pf[kB][kNChunk][kH][kD];
__device__ __align__(16) float g_pr[kB][kNChunk][kH][kD];

using u64 = unsigned long long;

__device__ __forceinline__ u64 pack2(float lo, float hi) {
    u64 r;
    asm("mov.b64 %0, {%1, %2};"
        : "=l"(r) : "r"(__float_as_uint(lo)), "r"(__float_as_uint(hi)));
    return r;
}
__device__ __forceinline__ u64 fma2(u64 a, u64 b, u64 c) {
    u64 r;
    asm("fma.rn.f32x2 %0, %1, %2, %3;" : "=l"(r) : "l"(a), "l"(b), "l"(c));
    return r;
}
__device__ __forceinline__ u64 add2(u64 a, u64 b) {
    u64 r;
    asm("add.rn.f32x2 %0, %1, %2;" : "=l"(r) : "l"(a), "l"(b));
    return r;
}
__device__ __forceinline__ void store_cs(u64* p, u64 v) {
    float2 f;
    f.x = __uint_as_float((unsigned)(v & 0xffffffffull));
    f.y = __uint_as_float((unsigned)(v >> 32));
    __stcs(reinterpret_cast<float2*>(p), f);
}

// fp32 sigmoid pair without cancellation: sig(v) and sig(-v) both direct.
__device__ __forceinline__ float sigp(float v) { return 1.0f / (1.0f + expf(-v)); }

// ---------------------------------------------------------------------------
// Phase 1: per-chunk local scans (zero-init), store end states (fwd + rev).
// Chunk x cached in SMEM; x read from global exactly once.
// ---------------------------------------------------------------------------
__global__ void __launch_bounds__(kThreads)
ema_phase1(const float* __restrict__ x,
           const float* __restrict__ al,  const float* __restrict__ da,
           const float* __restrict__ ral, const float* __restrict__ rda)
{
    __shared__ u64 sxv[kChunk * kThreads];         // 16 KB
    __shared__ float s_qf[kH], s_qr[kH];

    const int tid = threadIdx.x;
    if (tid < kH) {
        // 1 - sigmoid(v) computed as sigmoid(-v): no cancellation.
        s_qf[tid] = sigp(-al[tid])  * sigp(da[tid]);
        s_qr[tid] = sigp(-ral[tid]) * sigp(rda[tid]);
    }

    const int blk = blockIdx.x;
    const int dt = blk & (kDTiles - 1);
    const int c  = (blk >> 2) & (kNChunk - 1);
    const int b  = blk >> 9;

    const u64* xs = reinterpret_cast<const u64*>(
        x + ((size_t)b * kL + (size_t)c * kChunk) * kD + dt * kCols) + tid;
    const int d = dt * kCols + 2 * tid;

    __syncthreads();

    u64 q2[kH], s[kH];
#pragma unroll
    for (int h = 0; h < kH; ++h) {
        float q = s_qf[h];
        q2[h] = pack2(q, q);
        s[h] = 0ull;
    }

    // fwd pass: ascending, pull x from global, stash in smem
#pragma unroll
    for (int i = 0; i < kChunk; ++i) {
        u64 xv = xs[i * (kD / 2)];
        sxv[i * kThreads + tid] = xv;
#pragma unroll
        for (int h = 0; h < kH; ++h) s[h] = fma2(q2[h], s[h], xv);
    }
#pragma unroll
    for (int h = 0; h < kH; ++h)
        *reinterpret_cast<u64*>(&g_sf[b][c][h][d]) = s[h];

    // rev pass: descending over smem copy
#pragma unroll
    for (int h = 0; h < kH; ++h) {
        float q = s_qr[h];
        q2[h] = pack2(q, q);
        s[h] = 0ull;
    }
#pragma unroll
    for (int i = kChunk - 1; i >= 0; --i) {
        u64 xv = sxv[i * kThreads + tid];
#pragma unroll
        for (int h = 0; h < kH; ++h) s[h] = fma2(q2[h], s[h], xv);
    }
#pragma unroll
    for (int h = 0; h < kH; ++h)
        *reinterpret_cast<u64*>(&g_sr[b][c][h][d]) = s[h];
}

// ---------------------------------------------------------------------------
// Phase 2: chain chunk states with q^kChunk; emit per-chunk incoming prefixes.
// One thread per (b, dir, h, d). All traffic is L2-resident scratch.
// ---------------------------------------------------------------------------
__global__ void __launch_bounds__(256)
ema_phase2(const float* __restrict__ al,  const float* __restrict__ da,
           const float* __restrict__ ral, const float* __restrict__ rda)
{
    __shared__ float s_qc[2][kH];
    const int tid = threadIdx.x;
    if (tid < 2 * kH) {
        const int h = tid & (kH - 1);
        float q = (tid < kH) ? sigp(-al[h])  * sigp(da[h])
                             : sigp(-ral[h]) * sigp(rda[h]);
#pragma unroll
        for (int k = 0; k < 4; ++k) q *= q;    // q^16
        s_qc[tid >= kH][h] = q;
    }
    __syncthreads();

    const int t = blockIdx.x * blockDim.x + tid;   // 32768 total
    const int d   = t & (kD - 1);
    const int h   = (t >> 10) & (kH - 1);
    const int rev = (t >> 13) & 1;
    const int b   = t >> 14;

    const float qc = s_qc[rev][h];
    const int stride = kH * kD;
    const float* st = rev ? &g_sr[b][0][h][d] : &g_sf[b][0][h][d];
    float*       pr = rev ? &g_pr[b][0][h][d] : &g_pf[b][0][h][d];

    float p = 0.0f;
    if (!rev) {
        for (int c = 0; c < kNChunk; ++c) {
            pr[(size_t)c * stride] = p;
            p = fmaf(qc, p, st[(size_t)c * stride]);
        }
    } else {
        for (int c = kNChunk - 1; c >= 0; --c) {
            pr[(size_t)c * stride] = p;
            p = fmaf(qc, p, st[(size_t)c * stride]);
        }
    }
}

// ---------------------------------------------------------------------------
// Phase 3: rescan each chunk seeded with its prefix; apply fused weights
// w = expansion*reduction*a; out = fwd + rev, written once (streaming).
// Chunk x in SMEM (global read once, L2-hot from phase 1).
// ---------------------------------------------------------------------------
__global__ void __launch_bounds__(kThreads)
ema_phase3(const float* __restrict__ x,
           const float* __restrict__ ex,  const float* __restrict__ re,
           const float* __restrict__ al,  const float* __restrict__ da,
           const float* __restrict__ ral, const float* __restrict__ rda,
           float* __restrict__ out)
{
    __shared__ u64 sxv[kChunk * kThreads];   // 16 KB
    __shared__ u64 acc[kChunk * kThreads];   // 16 KB
    __shared__ float s_q[2][kH], s_a[2][kH];

    const int tid = threadIdx.x;
    if (tid < 2 * kH) {
        const int h = tid & (kH - 1);
        if (tid < kH) {
            s_a[0][h] = sigp(al[h]);
            s_q[0][h] = sigp(-al[h]) * sigp(da[h]);
        } else {
            s_a[1][h] = sigp(ral[h]);
            s_q[1][h] = sigp(-ral[h]) * sigp(rda[h]);
        }
    }

    const int blk = blockIdx.x;
    const int dt = blk & (kDTiles - 1);
    const int c  = (blk >> 2) & (kNChunk - 1);
    const int b  = blk >> 9;

    const u64* xs = reinterpret_cast<const u64*>(
        x + ((size_t)b * kL + (size_t)c * kChunk) * kD + dt * kCols) + tid;
    const int d = dt * kCols + 2 * tid;

    __syncthreads();

    // ---- forward pass ----
    u64 q2[kH], w[kH], u[kH];
#pragma unroll
    for (int h = 0; h < kH; ++h) {
        float q = s_q[0][h], a = s_a[0][h];
        q2[h] = pack2(q, q);
        float e0 = ex[h * kD + d], e1 = ex[h * kD + d + 1];
        float r0 = re[h * kD + d], r1 = re[h * kD + d + 1];
        w[h] = pack2(e0 * r0 * a, e1 * r1 * a);
        u[h] = *reinterpret_cast<const u64*>(&g_pf[b][c][h][d]);
    }

#pragma unroll
    for (int i = 0; i < kChunk; ++i) {
        u64 xv = xs[i * (kD / 2)];
        sxv[i * kThreads + tid] = xv;
        u64 fs = 0ull;
#pragma unroll
        for (int h = 0; h < kH; ++h) {
            u[h] = fma2(q2[h], u[h], xv);
            fs   = fma2(w[h], u[h], fs);
        }
        acc[i * kThreads + tid] = fs;
    }

    // ---- reverse pass ----
#pragma unroll
    for (int h = 0; h < kH; ++h) {
        float q = s_q[1][h], a = s_a[1][h];
        q2[h] = pack2(q, q);
        float e0 = ex[(kH + h) * kD + d], e1 = ex[(kH + h) * kD + d + 1];
        float r0 = re[(kH + h) * kD + d], r1 = re[(kH + h) * kD + d + 1];
        w[h] = pack2(e0 * r0 * a, e1 * r1 * a);
        u[h] = *reinterpret_cast<const u64*>(&g_pr[b][c][h][d]);
    }

    u64* od = reinterpret_cast<u64*>(
        out + ((size_t)b * kL + (size_t)c * kChunk) * kD + dt * kCols) + tid;

#pragma unroll
    for (int i = kChunk - 1; i >= 0; --i) {
        u64 xv = sxv[i * kThreads + tid];
        u64 rs = 0ull;
#pragma unroll
        for (int h = 0; h < kH; ++h) {
            u[h] = fma2(q2[h], u[h], xv);
            rs   = fma2(w[h], u[h], rs);
        }
        store_cs(od + i * (kD / 2), add2(acc[i * kThreads + tid], rs));
    }
}

// ---------------------------------------------------------------------------
extern "C" void kernel_launch(void* const* d_in, const int* in_sizes, int n_in,
                              void* d_out, int out_size)
{
    const float* x   = (const float*)d_in[0];
    const float* ex  = (const float*)d_in[1];
    const float* re  = (const float*)d_in[2];
    const float* al  = (const float*)d_in[3];
    const float* da  = (const float*)d_in[4];
    const float* ral = (const float*)d_in[5];
    const float* rda = (const float*)d_in[6];
    float* out = (float*)d_out;

    ema_phase1<<<kBlocks, kThreads>>>(x, al, da, ral, rda);
    ema_phase2<<<(kB * 2 * kH * kD) / 256, 256>>>(al, da, ral, rda);
    ema_phase3<<<kBlocks, kThreads>>>(x, ex, re, al, da, ral, rda, out);
}

// round 6
// speedup vs baseline: 12.6758x; 1.3568x over previous
#include <cuda_runtime.h>
#include <cstdint>

// ---------------------------------------------------------------------------
// MultiHeadedEMA == causal + anti-causal first-order EMA per (head, channel).
//   fwd: u[t] = q*u[t-1] + x[t] ;  rev: u[t] = q*u[t+1] + x[t]
//   out[b,l,d] = sum_h wf[h,d]*uf + wr[h,d]*ur,  w = expansion*reduction*a
// 3-phase chunked scan. Round-5: kChunk 16->32 (phase2 chain + scratch
// halved), phase1 rev pass re-reads x from L1 instead of smem staging,
// phase3 keeps acc in smem and streams the output.
// ---------------------------------------------------------------------------

constexpr int kB = 2;
constexpr int kL = 2048;
constexpr int kD = 1024;
constexpr int kH = 8;

constexpr int kChunk   = 32;
constexpr int kNChunk  = kL / kChunk;       // 64
constexpr int kCols    = 256;               // d-columns per block
constexpr int kThreads = 128;               // 2 cols/thread -> f32x2
constexpr int kDTiles  = kD / kCols;        // 4
constexpr int kBlocks  = kB * kNChunk * kDTiles;  // 512

// Scratch: per-chunk end states / incoming prefixes, fwd and rev. (16 MB, L2)
__device__ __align__(16) float g_sf[kB][kNChunk][kH][kD];
__device__ __align__(16) float g_sr[kB][kNChunk][kH][kD];
__device__ __align__(16) float g_pf[kB][kNChunk][kH][kD];
__device__ __align__(16) float g_pr[kB][kNChunk][kH][kD];

using u64 = unsigned long long;

__device__ __forceinline__ u64 pack2(float lo, float hi) {
    u64 r;
    asm("mov.b64 %0, {%1, %2};"
        : "=l"(r) : "r"(__float_as_uint(lo)), "r"(__float_as_uint(hi)));
    return r;
}
__device__ __forceinline__ u64 fma2(u64 a, u64 b, u64 c) {
    u64 r;
    asm("fma.rn.f32x2 %0, %1, %2, %3;" : "=l"(r) : "l"(a), "l"(b), "l"(c));
    return r;
}
__device__ __forceinline__ u64 add2(u64 a, u64 b) {
    u64 r;
    asm("add.rn.f32x2 %0, %1, %2;" : "=l"(r) : "l"(a), "l"(b));
    return r;
}
__device__ __forceinline__ void store_cs(u64* p, u64 v) {
    float2 f;
    f.x = __uint_as_float((unsigned)(v & 0xffffffffull));
    f.y = __uint_as_float((unsigned)(v >> 32));
    __stcs(reinterpret_cast<float2*>(p), f);
}

// fp32 sigmoid without cancellation: use sigp(-v) for the (1 - sigmoid(v)) term.
__device__ __forceinline__ float sigp(float v) { return 1.0f / (1.0f + expf(-v)); }

// ---------------------------------------------------------------------------
// Phase 1: per-chunk local scans (zero-init), store end states (fwd + rev).
// Rev pass re-reads the block's 32 KB x footprint from L1.
// ---------------------------------------------------------------------------
__global__ void __launch_bounds__(kThreads)
ema_phase1(const float* __restrict__ x,
           const float* __restrict__ al,  const float* __restrict__ da,
           const float* __restrict__ ral, const float* __restrict__ rda)
{
    __shared__ float s_qf[kH], s_qr[kH];

    const int tid = threadIdx.x;
    if (tid < kH) {
        s_qf[tid] = sigp(-al[tid])  * sigp(da[tid]);
        s_qr[tid] = sigp(-ral[tid]) * sigp(rda[tid]);
    }

    const int blk = blockIdx.x;
    const int dt = blk & (kDTiles - 1);
    const int c  = (blk >> 2) & (kNChunk - 1);
    const int b  = blk >> 8;

    const u64* xs = reinterpret_cast<const u64*>(
        x + ((size_t)b * kL + (size_t)c * kChunk) * kD + dt * kCols) + tid;
    const int d = dt * kCols + 2 * tid;

    __syncthreads();

    u64 q2[kH], s[kH];
#pragma unroll
    for (int h = 0; h < kH; ++h) {
        float q = s_qf[h];
        q2[h] = pack2(q, q);
        s[h] = 0ull;
    }
#pragma unroll
    for (int i = 0; i < kChunk; ++i) {
        u64 xv = xs[i * (kD / 2)];
#pragma unroll
        for (int h = 0; h < kH; ++h) s[h] = fma2(q2[h], s[h], xv);
    }
#pragma unroll
    for (int h = 0; h < kH; ++h)
        *reinterpret_cast<u64*>(&g_sf[b][c][h][d]) = s[h];

#pragma unroll
    for (int h = 0; h < kH; ++h) {
        float q = s_qr[h];
        q2[h] = pack2(q, q);
        s[h] = 0ull;
    }
#pragma unroll
    for (int i = kChunk - 1; i >= 0; --i) {
        u64 xv = xs[i * (kD / 2)];        // L1 hit (same addresses as fwd pass)
#pragma unroll
        for (int h = 0; h < kH; ++h) s[h] = fma2(q2[h], s[h], xv);
    }
#pragma unroll
    for (int h = 0; h < kH; ++h)
        *reinterpret_cast<u64*>(&g_sr[b][c][h][d]) = s[h];
}

// ---------------------------------------------------------------------------
// Phase 2: chain chunk states with q^kChunk (64-long serial chain); emit
// per-chunk incoming prefixes. One thread per (b, dir, h, d); L2-resident.
// ---------------------------------------------------------------------------
__global__ void __launch_bounds__(256)
ema_phase2(const float* __restrict__ al,  const float* __restrict__ da,
           const float* __restrict__ ral, const float* __restrict__ rda)
{
    __shared__ float s_qc[2][kH];
    const int tid = threadIdx.x;
    if (tid < 2 * kH) {
        const int h = tid & (kH - 1);
        float q = (tid < kH) ? sigp(-al[h])  * sigp(da[h])
                             : sigp(-ral[h]) * sigp(rda[h]);
#pragma unroll
        for (int k = 0; k < 5; ++k) q *= q;    // q^32 (kChunk = 32)
        s_qc[tid >= kH][h] = q;
    }
    __syncthreads();

    const int t = blockIdx.x * blockDim.x + tid;   // 32768 total
    const int d   = t & (kD - 1);
    const int h   = (t >> 10) & (kH - 1);
    const int rev = (t >> 13) & 1;
    const int b   = t >> 14;

    const float qc = s_qc[rev][h];
    const int stride = kH * kD;
    const float* st = rev ? &g_sr[b][0][h][d] : &g_sf[b][0][h][d];
    float*       pr = rev ? &g_pr[b][0][h][d] : &g_pf[b][0][h][d];

    float p = 0.0f;
    if (!rev) {
#pragma unroll 8
        for (int c = 0; c < kNChunk; ++c) {
            pr[(size_t)c * stride] = p;
            p = fmaf(qc, p, st[(size_t)c * stride]);
        }
    } else {
#pragma unroll 8
        for (int c = kNChunk - 1; c >= 0; --c) {
            pr[(size_t)c * stride] = p;
            p = fmaf(qc, p, st[(size_t)c * stride]);
        }
    }
}

// ---------------------------------------------------------------------------
// Phase 3: rescan each chunk seeded with its prefix; apply fused weights
// w = expansion*reduction*a; out = fwd + rev, written once (streaming).
// fwd x reads hit L2 (resident from phase1); rev re-reads hit L1.
// ---------------------------------------------------------------------------
__global__ void __launch_bounds__(kThreads)
ema_phase3(const float* __restrict__ x,
           const float* __restrict__ ex,  const float* __restrict__ re,
           const float* __restrict__ al,  const float* __restrict__ da,
           const float* __restrict__ ral, const float* __restrict__ rda,
           float* __restrict__ out)
{
    __shared__ u64 acc[kChunk * kThreads];   // 32 KB
    __shared__ float s_q[2][kH], s_a[2][kH];

    const int tid = threadIdx.x;
    if (tid < 2 * kH) {
        const int h = tid & (kH - 1);
        if (tid < kH) {
            s_a[0][h] = sigp(al[h]);
            s_q[0][h] = sigp(-al[h]) * sigp(da[h]);
        } else {
            s_a[1][h] = sigp(ral[h]);
            s_q[1][h] = sigp(-ral[h]) * sigp(rda[h]);
        }
    }

    const int blk = blockIdx.x;
    const int dt = blk & (kDTiles - 1);
    const int c  = (blk >> 2) & (kNChunk - 1);
    const int b  = blk >> 8;

    const u64* xs = reinterpret_cast<const u64*>(
        x + ((size_t)b * kL + (size_t)c * kChunk) * kD + dt * kCols) + tid;
    const int d = dt * kCols + 2 * tid;

    __syncthreads();

    // ---- forward pass ----
    u64 q2[kH], w[kH], u[kH];
#pragma unroll
    for (int h = 0; h < kH; ++h) {
        float q = s_q[0][h], a = s_a[0][h];
        q2[h] = pack2(q, q);
        float e0 = ex[h * kD + d], e1 = ex[h * kD + d + 1];
        float r0 = re[h * kD + d], r1 = re[h * kD + d + 1];
        w[h] = pack2(e0 * r0 * a, e1 * r1 * a);
        u[h] = *reinterpret_cast<const u64*>(&g_pf[b][c][h][d]);
    }

#pragma unroll
    for (int i = 0; i < kChunk; ++i) {
        u64 xv = xs[i * (kD / 2)];
        u64 fs = 0ull;
#pragma unroll
        for (int h = 0; h < kH; ++h) {
            u[h] = fma2(q2[h], u[h], xv);
            fs   = fma2(w[h], u[h], fs);
        }
        acc[i * kThreads + tid] = fs;
    }

    // ---- reverse pass ----
#pragma unroll
    for (int h = 0; h < kH; ++h) {
        float q = s_q[1][h], a = s_a[1][h];
        q2[h] = pack2(q, q);
        float e0 = ex[(kH + h) * kD + d], e1 = ex[(kH + h) * kD + d + 1];
        float r0 = re[(kH + h) * kD + d], r1 = re[(kH + h) * kD + d + 1];
        w[h] = pack2(e0 * r0 * a, e1 * r1 * a);
        u[h] = *reinterpret_cast<const u64*>(&g_pr[b][c][h][d]);
    }

    u64* od = reinterpret_cast<u64*>(
        out + ((size_t)b * kL + (size_t)c * kChunk) * kD + dt * kCols) + tid;

#pragma unroll
    for (int i = kChunk - 1; i >= 0; --i) {
        u64 xv = xs[i * (kD / 2)];        // L1 hit
        u64 rs = 0ull;
#pragma unroll
        for (int h = 0; h < kH; ++h) {
            u[h] = fma2(q2[h], u[h], xv);
            rs   = fma2(w[h], u[h], rs);
        }
        store_cs(od + i * (kD / 2), add2(acc[i * kThreads + tid], rs));
    }
}

// ---------------------------------------------------------------------------
extern "C" void kernel_launch(void* const* d_in, const int* in_sizes, int n_in,
                              void* d_out, int out_size)
{
    const float* x   = (const float*)d_in[0];
    const float* ex  = (const float*)d_in[1];
    const float* re  = (const float*)d_in[2];
    const float* al  = (const float*)d_in[3];
    const float* da  = (const float*)d_in[4];
    const float* ral = (const float*)d_in[5];
    const float* rda = (const float*)d_in[6];
    float* out = (float*)d_out;

    ema_phase1<<<kBlocks, kThreads>>>(x, al, da, ral, rda);
    ema_phase2<<<(kB * 2 * kH * kD) / 256, 256>>>(al, da, ral, rda);
    ema_phase3<<<kBlocks, kThreads>>>(x, ex, re, al, da, ral, rda, out);
}

// round 7
// speedup vs baseline: 12.9380x; 1.0207x over previous
#include <cuda_runtime.h>
#include <cstdint>

// ---------------------------------------------------------------------------
// MultiHeadedEMA == causal + anti-causal first-order EMA per (head, channel).
//   fwd: u[t] = q*u[t-1] + x[t] ;  rev: u[t] = q*u[t+1] + x[t]
//   out[b,l,d] = sum_h wf[h,d]*uf + wr[h,d]*ur,  w = expansion*reduction*a
// Round-6: single fused kernel with software grid barriers.
//   - x tile loaded from DRAM once into 64 KB smem, reused by all 4 scan passes
//   - phase3 fwd streams to out; rev pass RMWs the L2-hot line (no acc buffer)
//   - 256 blocks x 256 threads, 2 blocks/SM guaranteed co-resident
// ---------------------------------------------------------------------------

constexpr int kB = 2;
constexpr int kL = 2048;
constexpr int kD = 1024;
constexpr int kH = 8;

constexpr int kChunk   = 32;
constexpr int kNChunk  = kL / kChunk;             // 64
constexpr int kCols    = 512;                     // d-columns per block
constexpr int kThreads = 256;                     // 2 cols/thread -> f32x2
constexpr int kDTiles  = kD / kCols;              // 2
constexpr int kBlocks  = kB * kNChunk * kDTiles;  // 256
constexpr int kSmem    = kChunk * kThreads * 8;   // 64 KB x-tile

// Scratch: per-chunk end states / incoming prefixes, fwd and rev (L2-resident).
__device__ __align__(16) float g_sf[kB][kNChunk][kH][kD];
__device__ __align__(16) float g_sr[kB][kNChunk][kH][kD];
__device__ __align__(16) float g_pf[kB][kNChunk][kH][kD];
__device__ __align__(16) float g_pr[kB][kNChunk][kH][kD];

// Grid-barrier counters (monotonic; each launch adds exactly kBlocks).
__device__ unsigned g_bar[2];

using u64 = unsigned long long;

__device__ __forceinline__ u64 pack2(float lo, float hi) {
    u64 r;
    asm("mov.b64 %0, {%1, %2};"
        : "=l"(r) : "r"(__float_as_uint(lo)), "r"(__float_as_uint(hi)));
    return r;
}
__device__ __forceinline__ u64 fma2(u64 a, u64 b, u64 c) {
    u64 r;
    asm("fma.rn.f32x2 %0, %1, %2, %3;" : "=l"(r) : "l"(a), "l"(b), "l"(c));
    return r;
}
__device__ __forceinline__ u64 add2(u64 a, u64 b) {
    u64 r;
    asm("add.rn.f32x2 %0, %1, %2;" : "=l"(r) : "l"(a), "l"(b));
    return r;
}
__device__ __forceinline__ void store_cs(u64* p, u64 v) {
    float2 f;
    f.x = __uint_as_float((unsigned)(v & 0xffffffffull));
    f.y = __uint_as_float((unsigned)(v >> 32));
    __stcs(reinterpret_cast<float2*>(p), f);
}
__device__ __forceinline__ u64 load_cs(const u64* p) {
    float2 f = __ldcs(reinterpret_cast<const float2*>(p));
    return pack2(f.x, f.y);
}

// fp32 sigmoid; use sigp(-v) for the (1 - sigmoid(v)) term (no cancellation).
__device__ __forceinline__ float sigp(float v) { return 1.0f / (1.0f + expf(-v)); }

// libcudacxx-style grid barrier: wrap-safe, graph-replay-safe.
__device__ __forceinline__ void grid_barrier(int idx) {
    __syncthreads();
    if (threadIdx.x == 0) {
        __threadfence();                               // release
        unsigned t = atomicAdd(&g_bar[idx], 1u);
        unsigned target = t - (t % kBlocks) + kBlocks; // this launch's epoch end
        volatile unsigned* p = &g_bar[idx];
        while ((int)(*p - target) < 0) { }
    }
    __syncthreads();
}

// ---------------------------------------------------------------------------
__global__ void __launch_bounds__(kThreads, 2)
ema_fused(const float* __restrict__ x,
          const float* __restrict__ ex,  const float* __restrict__ re,
          const float* __restrict__ al,  const float* __restrict__ da,
          const float* __restrict__ ral, const float* __restrict__ rda,
          float* __restrict__ out)
{
    extern __shared__ u64 sx[];                 // 64 KB: kChunk x kThreads u64
    __shared__ float s_q[2][kH], s_a[2][kH];

    const int tid = threadIdx.x;
    if (tid < 2 * kH) {
        const int h = tid & (kH - 1);
        if (tid < kH) {
            s_a[0][h] = sigp(al[h]);
            s_q[0][h] = sigp(-al[h]) * sigp(da[h]);
        } else {
            s_a[1][h] = sigp(ral[h]);
            s_q[1][h] = sigp(-ral[h]) * sigp(rda[h]);
        }
    }

    const int blk = blockIdx.x;
    const int dt = blk & (kDTiles - 1);
    const int c  = (blk >> 1) & (kNChunk - 1);
    const int b  = blk >> 7;

    const u64* xs = reinterpret_cast<const u64*>(
        x + ((size_t)b * kL + (size_t)c * kChunk) * kD + dt * kCols) + tid;
    const int d = dt * kCols + 2 * tid;

    __syncthreads();

    // ================= phase 1: local scans, store chunk end states ========
    {
        u64 q2[kH], s[kH];
#pragma unroll
        for (int h = 0; h < kH; ++h) {
            float q = s_q[0][h];
            q2[h] = pack2(q, q);
            s[h] = 0ull;
        }
#pragma unroll
        for (int i = 0; i < kChunk; ++i) {
            u64 xv = xs[i * (kD / 2)];        // DRAM read (only global x read)
            sx[i * kThreads + tid] = xv;
#pragma unroll
            for (int h = 0; h < kH; ++h) s[h] = fma2(q2[h], s[h], xv);
        }
#pragma unroll
        for (int h = 0; h < kH; ++h)
            *reinterpret_cast<u64*>(&g_sf[b][c][h][d]) = s[h];

#pragma unroll
        for (int h = 0; h < kH; ++h) {
            float q = s_q[1][h];
            q2[h] = pack2(q, q);
            s[h] = 0ull;
        }
#pragma unroll
        for (int i = kChunk - 1; i >= 0; --i) {
            u64 xv = sx[i * kThreads + tid];  // smem
#pragma unroll
            for (int h = 0; h < kH; ++h) s[h] = fma2(q2[h], s[h], xv);
        }
#pragma unroll
        for (int h = 0; h < kH; ++h)
            *reinterpret_cast<u64*>(&g_sr[b][c][h][d]) = s[h];
    }

    grid_barrier(0);

    // ================= phase 2: chain chunk states with q^kChunk ============
    // 32768 lanes = 256 blocks x 128 threads (tid < 128), coalesced over d.
    if (tid < 128) {
        const int t2  = blk * 128 + tid;
        const int dd  = t2 & (kD - 1);
        const int h   = (t2 >> 10) & (kH - 1);
        const int rev = (t2 >> 13) & 1;
        const int bb  = t2 >> 14;

        float qc = s_q[rev][h];
#pragma unroll
        for (int k = 0; k < 5; ++k) qc *= qc;          // q^32

        const int stride = kH * kD;
        const float* st = rev ? &g_sr[bb][0][h][dd] : &g_sf[bb][0][h][dd];
        float*       pr = rev ? &g_pr[bb][0][h][dd] : &g_pf[bb][0][h][dd];

        float p = 0.0f;
        if (!rev) {
#pragma unroll 8
            for (int cc = 0; cc < kNChunk; ++cc) {
                pr[(size_t)cc * stride] = p;
                p = fmaf(qc, p, st[(size_t)cc * stride]);
            }
        } else {
#pragma unroll 8
            for (int cc = kNChunk - 1; cc >= 0; --cc) {
                pr[(size_t)cc * stride] = p;
                p = fmaf(qc, p, st[(size_t)cc * stride]);
            }
        }
    }

    grid_barrier(1);

    // ================= phase 3: seeded rescan + fused output ================
    u64* od = reinterpret_cast<u64*>(
        out + ((size_t)b * kL + (size_t)c * kChunk) * kD + dt * kCols) + tid;

    {
        // ---- forward: stream fs to out ----
        u64 q2[kH], w[kH], u[kH];
#pragma unroll
        for (int h = 0; h < kH; ++h) {
            float q = s_q[0][h], a = s_a[0][h];
            q2[h] = pack2(q, q);
            float e0 = ex[h * kD + d], e1 = ex[h * kD + d + 1];
            float r0 = re[h * kD + d], r1 = re[h * kD + d + 1];
            w[h] = pack2(e0 * r0 * a, e1 * r1 * a);
            u[h] = *reinterpret_cast<const u64*>(&g_pf[b][c][h][d]);
        }
#pragma unroll
        for (int i = 0; i < kChunk; ++i) {
            u64 xv = sx[i * kThreads + tid];  // smem
            u64 fs = 0ull;
#pragma unroll
            for (int h = 0; h < kH; ++h) {
                u[h] = fma2(q2[h], u[h], xv);
                fs   = fma2(w[h], u[h], fs);
            }
            store_cs(od + i * (kD / 2), fs);
        }

        // ---- reverse: RMW out (same-thread, L2-hot) ----
#pragma unroll
        for (int h = 0; h < kH; ++h) {
            float q = s_q[1][h], a = s_a[1][h];
            q2[h] = pack2(q, q);
            float e0 = ex[(kH + h) * kD + d], e1 = ex[(kH + h) * kD + d + 1];
            float r0 = re[(kH + h) * kD + d], r1 = re[(kH + h) * kD + d + 1];
            w[h] = pack2(e0 * r0 * a, e1 * r1 * a);
            u[h] = *reinterpret_cast<const u64*>(&g_pr[b][c][h][d]);
        }
#pragma unroll
        for (int i = kChunk - 1; i >= 0; --i) {
            u64 xv = sx[i * kThreads + tid];  // smem
            u64 rs = 0ull;
#pragma unroll
            for (int h = 0; h < kH; ++h) {
                u[h] = fma2(q2[h], u[h], xv);
                rs   = fma2(w[h], u[h], rs);
            }
            u64 prev = load_cs(od + i * (kD / 2));
            store_cs(od + i * (kD / 2), add2(prev, rs));
        }
    }
}

// ---------------------------------------------------------------------------
extern "C" void kernel_launch(void* const* d_in, const int* in_sizes, int n_in,
                              void* d_out, int out_size)
{
    const float* x   = (const float*)d_in[0];
    const float* ex  = (const float*)d_in[1];
    const float* re  = (const float*)d_in[2];
    const float* al  = (const float*)d_in[3];
    const float* da  = (const float*)d_in[4];
    const float* ral = (const float*)d_in[5];
    const float* rda = (const float*)d_in[6];
    float* out = (float*)d_out;

    static bool attr_done = false;
    if (!attr_done) {
        cudaFuncSetAttribute(ema_fused,
                             cudaFuncAttributeMaxDynamicSharedMemorySize, kSmem);
        attr_done = true;
    }
    ema_fused<<<kBlocks, kThreads, kSmem>>>(x, ex, re, al, da, ral, rda, out);
}

// round 8
// speedup vs baseline: 23.9783x; 1.8533x over previous
#include <cuda_runtime.h>
#include <cstdint>

// ---------------------------------------------------------------------------
// MultiHeadedEMA == causal + anti-causal first-order EMA per (head, channel).
//   fwd: u[t] = q*u[t-1] + x[t] ;  rev: u[t] = q*u[t+1] + x[t]
//   out[b,l,d] = sum_h wf[h,d]*uf + wr[h,d]*ur,  w = expansion*reduction*a
// Round-7: single kernel, ONE grid barrier, phase2 replaced by windowed
// lookback over chunk aggregates (geometric weights qc^k truncate in ~2-6
// terms; falls back to full sum if q ~ 1). 512 blocks x 128 threads,
// 4 blocks/SM co-resident.
// ---------------------------------------------------------------------------

constexpr int kB = 2;
constexpr int kL = 2048;
constexpr int kD = 1024;
constexpr int kH = 8;

constexpr int kChunk   = 32;
constexpr int kNChunk  = kL / kChunk;             // 64
constexpr int kCols    = 256;                     // d-columns per block
constexpr int kThreads = 128;                     // 2 cols/thread -> f32x2
constexpr int kDTiles  = kD / kCols;              // 4
constexpr int kBlocks  = kB * kNChunk * kDTiles;  // 512

// Per-chunk end states (fwd / rev), L2-resident scratch (8 MB).
__device__ __align__(16) float g_sf[kB][kNChunk][kH][kD];
__device__ __align__(16) float g_sr[kB][kNChunk][kH][kD];

// Grid-barrier counter (monotonic; each launch adds exactly kBlocks).
__device__ unsigned g_bar;

using u64 = unsigned long long;

__device__ __forceinline__ u64 pack2(float lo, float hi) {
    u64 r;
    asm("mov.b64 %0, {%1, %2};"
        : "=l"(r) : "r"(__float_as_uint(lo)), "r"(__float_as_uint(hi)));
    return r;
}
__device__ __forceinline__ u64 fma2(u64 a, u64 b, u64 c) {
    u64 r;
    asm("fma.rn.f32x2 %0, %1, %2, %3;" : "=l"(r) : "l"(a), "l"(b), "l"(c));
    return r;
}
__device__ __forceinline__ u64 add2(u64 a, u64 b) {
    u64 r;
    asm("add.rn.f32x2 %0, %1, %2;" : "=l"(r) : "l"(a), "l"(b));
    return r;
}
__device__ __forceinline__ void store_cs(u64* p, u64 v) {
    float2 f;
    f.x = __uint_as_float((unsigned)(v & 0xffffffffull));
    f.y = __uint_as_float((unsigned)(v >> 32));
    __stcs(reinterpret_cast<float2*>(p), f);
}
__device__ __forceinline__ u64 load_cs(const u64* p) {
    float2 f = __ldcs(reinterpret_cast<const float2*>(p));
    return pack2(f.x, f.y);
}

// fp32 sigmoid; use sigp(-v) for the (1 - sigmoid(v)) term (no cancellation).
__device__ __forceinline__ float sigp(float v) { return 1.0f / (1.0f + expf(-v)); }

// ---------------------------------------------------------------------------
__global__ void __launch_bounds__(kThreads, 4)
ema_fused(const float* __restrict__ x,
          const float* __restrict__ ex,  const float* __restrict__ re,
          const float* __restrict__ al,  const float* __restrict__ da,
          const float* __restrict__ ral, const float* __restrict__ rda,
          float* __restrict__ out)
{
    __shared__ u64 sx[kChunk * kThreads];            // 32 KB x-tile
    __shared__ float s_q[2][kH], s_a[2][kH], s_qc[2][kH], s_qcmax[2];

    const int tid = threadIdx.x;
    if (tid < 2 * kH) {
        const int dir = tid >= kH;
        const int h   = tid & (kH - 1);
        const float av = dir ? ral[h] : al[h];
        const float dv = dir ? rda[h] : da[h];
        s_a[dir][h] = sigp(av);
        float q = sigp(-av) * sigp(dv);
        s_q[dir][h] = q;
        float qc = q;
#pragma unroll
        for (int k = 0; k < 5; ++k) qc *= qc;        // q^32
        s_qc[dir][h] = qc;
    }
    if (tid < 2) s_qcmax[tid] = 0.0f;

    const int blk = blockIdx.x;
    const int dt = blk & (kDTiles - 1);
    const int c  = (blk >> 2) & (kNChunk - 1);
    const int b  = blk >> 8;

    const u64* xs = reinterpret_cast<const u64*>(
        x + ((size_t)b * kL + (size_t)c * kChunk) * kD + dt * kCols) + tid;
    const int d = dt * kCols + 2 * tid;

    __syncthreads();
    if (tid < 2) {
        float m = 0.0f;
#pragma unroll
        for (int h = 0; h < kH; ++h) m = fmaxf(m, s_qc[tid][h]);
        s_qcmax[tid] = m;
    }

    // ================= phase 1: local scans, publish chunk end states ======
    {
        u64 q2[kH], s[kH];
#pragma unroll
        for (int h = 0; h < kH; ++h) {
            float q = s_q[0][h];
            q2[h] = pack2(q, q);
            s[h] = 0ull;
        }
#pragma unroll
        for (int i = 0; i < kChunk; ++i) {
            float2 xf = __ldcs(reinterpret_cast<const float2*>(xs + i * (kD / 2)));
            u64 xv = pack2(xf.x, xf.y);
            sx[i * kThreads + tid] = xv;
#pragma unroll
            for (int h = 0; h < kH; ++h) s[h] = fma2(q2[h], s[h], xv);
        }
#pragma unroll
        for (int h = 0; h < kH; ++h)
            *reinterpret_cast<u64*>(&g_sf[b][c][h][d]) = s[h];

#pragma unroll
        for (int h = 0; h < kH; ++h) {
            float q = s_q[1][h];
            q2[h] = pack2(q, q);
            s[h] = 0ull;
        }
#pragma unroll
        for (int i = kChunk - 1; i >= 0; --i) {
            u64 xv = sx[i * kThreads + tid];
#pragma unroll
            for (int h = 0; h < kH; ++h) s[h] = fma2(q2[h], s[h], xv);
        }
#pragma unroll
        for (int h = 0; h < kH; ++h)
            *reinterpret_cast<u64*>(&g_sr[b][c][h][d]) = s[h];
    }

    // ================= grid barrier (single) ================================
    __threadfence();                                   // release all stores
    __syncthreads();
    if (tid == 0) {
        unsigned t = atomicAdd(&g_bar, 1u);
        unsigned target = t - (t % kBlocks) + kBlocks; // this launch's epoch
        volatile unsigned* p = &g_bar;
        while ((int)(*p - target) < 0) { }
    }
    __syncthreads();

    const int dh = d >> 1;   // u64 column index
    const u64* bsf = reinterpret_cast<const u64*>(g_sf) +
                     (size_t)b * kNChunk * kH * (kD / 2) + dh;
    const u64* bsr = reinterpret_cast<const u64*>(g_sr) +
                     (size_t)b * kNChunk * kH * (kD / 2) + dh;

    u64* od = reinterpret_cast<u64*>(
        out + ((size_t)b * kL + (size_t)c * kChunk) * kD + dt * kCols) + tid;

    // ================= phase 3a: forward (lookback prefix + rescan) ========
    {
        u64 u[kH];
        float wk[kH];
#pragma unroll
        for (int h = 0; h < kH; ++h) { u[h] = 0ull; wk[h] = 1.0f; }
        const float qmax = s_qcmax[0];
        float wm = 1.0f;
        for (int k = 0; k < c; ++k) {                  // windowed lookback
            const u64* row = bsf + (size_t)(c - 1 - k) * kH * (kD / 2);
#pragma unroll
            for (int h = 0; h < kH; ++h) {
                u64 sv = row[h * (kD / 2)];
                u[h] = fma2(pack2(wk[h], wk[h]), sv, u[h]);
                wk[h] *= s_qc[0][h];
            }
            wm *= qmax;
            if (wm < 1e-8f) break;                     // uniform per block
        }

        u64 q2[kH], w[kH];
#pragma unroll
        for (int h = 0; h < kH; ++h) {
            float q = s_q[0][h], a = s_a[0][h];
            q2[h] = pack2(q, q);
            float e0 = ex[h * kD + d], e1 = ex[h * kD + d + 1];
            float r0 = re[h * kD + d], r1 = re[h * kD + d + 1];
            w[h] = pack2(e0 * r0 * a, e1 * r1 * a);
        }
#pragma unroll
        for (int i = 0; i < kChunk; ++i) {
            u64 xv = sx[i * kThreads + tid];
            u64 fs = 0ull;
#pragma unroll
            for (int h = 0; h < kH; ++h) {
                u[h] = fma2(q2[h], u[h], xv);
                fs   = fma2(w[h], u[h], fs);
            }
            store_cs(od + i * (kD / 2), fs);
        }
    }

    // ================= phase 3b: reverse (lookback prefix + rescan, RMW) ===
    {
        u64 u[kH];
        float wk[kH];
#pragma unroll
        for (int h = 0; h < kH; ++h) { u[h] = 0ull; wk[h] = 1.0f; }
        const float qmax = s_qcmax[1];
        float wm = 1.0f;
        for (int k = 0; k < kNChunk - 1 - c; ++k) {    // successors
            const u64* row = bsr + (size_t)(c + 1 + k) * kH * (kD / 2);
#pragma unroll
            for (int h = 0; h < kH; ++h) {
                u64 sv = row[h * (kD / 2)];
                u[h] = fma2(pack2(wk[h], wk[h]), sv, u[h]);
                wk[h] *= s_qc[1][h];
            }
            wm *= qmax;
            if (wm < 1e-8f) break;
        }

        u64 q2[kH], w[kH];
#pragma unroll
        for (int h = 0; h < kH; ++h) {
            float q = s_q[1][h], a = s_a[1][h];
            q2[h] = pack2(q, q);
            float e0 = ex[(kH + h) * kD + d], e1 = ex[(kH + h) * kD + d + 1];
            float r0 = re[(kH + h) * kD + d], r1 = re[(kH + h) * kD + d + 1];
            w[h] = pack2(e0 * r0 * a, e1 * r1 * a);
        }
#pragma unroll
        for (int i = kChunk - 1; i >= 0; --i) {
            u64 xv = sx[i * kThreads + tid];
            u64 rs = 0ull;
#pragma unroll
            for (int h = 0; h < kH; ++h) {
                u[h] = fma2(q2[h], u[h], xv);
                rs   = fma2(w[h], u[h], rs);
            }
            u64 prev = load_cs(od + i * (kD / 2));     // same-thread, L2-hot
            store_cs(od + i * (kD / 2), add2(prev, rs));
        }
    }
}

// ---------------------------------------------------------------------------
extern "C" void kernel_launch(void* const* d_in, const int* in_sizes, int n_in,
                              void* d_out, int out_size)
{
    const float* x   = (const float*)d_in[0];
    const float* ex  = (const float*)d_in[1];
    const float* re  = (const float*)d_in[2];
    const float* al  = (const float*)d_in[3];
    const float* da  = (const float*)d_in[4];
    const float* ral = (const float*)d_in[5];
    const float* rda = (const float*)d_in[6];
    float* out = (float*)d_out;

    ema_fused<<<kBlocks, kThreads>>>(x, ex, re, al, da, ral, rda, out);
}

// round 9
// speedup vs baseline: 24.0184x; 1.0017x over previous
#include <cuda_runtime.h>
#include <cstdint>

// ---------------------------------------------------------------------------
// MultiHeadedEMA == causal + anti-causal first-order EMA per (head, channel).
//   fwd: u[t] = q*u[t-1] + x[t] ;  rev: u[t] = q*u[t+1] + x[t]
//   out[b,l,d] = sum_h wf[h,d]*uf + wr[h,d]*ur,  w = expansion*reduction*a
// Round-8 -> 9: removed the out RMW (smem acc buffer, out stored once),
// x kept L1-resident (no .cs) so all rescans hit L1. One grid barrier,
// windowed lookback for cross-chunk prefixes.
// ---------------------------------------------------------------------------

constexpr int kB = 2;
constexpr int kL = 2048;
constexpr int kD = 1024;
constexpr int kH = 8;

constexpr int kChunk   = 32;
constexpr int kNChunk  = kL / kChunk;             // 64
constexpr int kCols    = 256;                     // d-columns per block
constexpr int kThreads = 128;                     // 2 cols/thread -> f32x2
constexpr int kDTiles  = kD / kCols;              // 4
constexpr int kBlocks  = kB * kNChunk * kDTiles;  // 512

// Per-chunk end states (fwd / rev), L2-resident scratch (8 MB).
__device__ __align__(16) float g_sf[kB][kNChunk][kH][kD];
__device__ __align__(16) float g_sr[kB][kNChunk][kH][kD];

// Grid-barrier counter (monotonic; each launch adds exactly kBlocks).
__device__ unsigned g_bar;

using u64 = unsigned long long;

__device__ __forceinline__ u64 pack2(float lo, float hi) {
    u64 r;
    asm("mov.b64 %0, {%1, %2};"
        : "=l"(r) : "r"(__float_as_uint(lo)), "r"(__float_as_uint(hi)));
    return r;
}
__device__ __forceinline__ u64 fma2(u64 a, u64 b, u64 c) {
    u64 r;
    asm("fma.rn.f32x2 %0, %1, %2, %3;" : "=l"(r) : "l"(a), "l"(b), "l"(c));
    return r;
}
__device__ __forceinline__ u64 add2(u64 a, u64 b) {
    u64 r;
    asm("add.rn.f32x2 %0, %1, %2;" : "=l"(r) : "l"(a), "l"(b));
    return r;
}
__device__ __forceinline__ void store_cs(u64* p, u64 v) {
    float2 f;
    f.x = __uint_as_float((unsigned)(v & 0xffffffffull));
    f.y = __uint_as_float((unsigned)(v >> 32));
    __stcs(reinterpret_cast<float2*>(p), f);
}

// fp32 sigmoid; use sigp(-v) for the (1 - sigmoid(v)) term (no cancellation).
__device__ __forceinline__ float sigp(float v) { return 1.0f / (1.0f + expf(-v)); }

// ---------------------------------------------------------------------------
__global__ void __launch_bounds__(kThreads, 4)
ema_fused(const float* __restrict__ x,
          const float* __restrict__ ex,  const float* __restrict__ re,
          const float* __restrict__ al,  const float* __restrict__ da,
          const float* __restrict__ ral, const float* __restrict__ rda,
          float* __restrict__ out)
{
    __shared__ u64 acc[kChunk * kThreads];           // 32 KB fwd partials
    __shared__ float s_q[2][kH], s_a[2][kH], s_qc[2][kH], s_qcmax[2];

    const int tid = threadIdx.x;
    if (tid < 2 * kH) {
        const int dir = tid >= kH;
        const int h   = tid & (kH - 1);
        const float av = dir ? ral[h] : al[h];
        const float dv = dir ? rda[h] : da[h];
        s_a[dir][h] = sigp(av);
        float q = sigp(-av) * sigp(dv);
        s_q[dir][h] = q;
        float qc = q;
#pragma unroll
        for (int k = 0; k < 5; ++k) qc *= qc;        // q^32
        s_qc[dir][h] = qc;
    }
    if (tid < 2) s_qcmax[tid] = 0.0f;

    const int blk = blockIdx.x;
    const int dt = blk & (kDTiles - 1);
    const int c  = (blk >> 2) & (kNChunk - 1);
    const int b  = blk >> 8;

    const u64* xs = reinterpret_cast<const u64*>(
        x + ((size_t)b * kL + (size_t)c * kChunk) * kD + dt * kCols) + tid;
    const int d = dt * kCols + 2 * tid;

    __syncthreads();
    if (tid < 2) {
        float m = 0.0f;
#pragma unroll
        for (int h = 0; h < kH; ++h) m = fmaxf(m, s_qc[tid][h]);
        s_qcmax[tid] = m;
    }

    // ================= phase 1: local scans, publish chunk end states ======
    {
        u64 q2[kH], s[kH];
#pragma unroll
        for (int h = 0; h < kH; ++h) {
            float q = s_q[0][h];
            q2[h] = pack2(q, q);
            s[h] = 0ull;
        }
#pragma unroll
        for (int i = 0; i < kChunk; ++i) {
            u64 xv = xs[i * (kD / 2)];               // DRAM/L2, warms L1
#pragma unroll
            for (int h = 0; h < kH; ++h) s[h] = fma2(q2[h], s[h], xv);
        }
#pragma unroll
        for (int h = 0; h < kH; ++h)
            *reinterpret_cast<u64*>(&g_sf[b][c][h][d]) = s[h];

#pragma unroll
        for (int h = 0; h < kH; ++h) {
            float q = s_q[1][h];
            q2[h] = pack2(q, q);
            s[h] = 0ull;
        }
#pragma unroll
        for (int i = kChunk - 1; i >= 0; --i) {
            u64 xv = xs[i * (kD / 2)];               // L1 hit
#pragma unroll
            for (int h = 0; h < kH; ++h) s[h] = fma2(q2[h], s[h], xv);
        }
#pragma unroll
        for (int h = 0; h < kH; ++h)
            *reinterpret_cast<u64*>(&g_sr[b][c][h][d]) = s[h];
    }

    // ================= grid barrier (single) ================================
    __threadfence();                                   // release all stores
    __syncthreads();
    if (tid == 0) {
        unsigned t = atomicAdd(&g_bar, 1u);
        unsigned target = t - (t % kBlocks) + kBlocks; // this launch's epoch
        volatile unsigned* p = &g_bar;
        while ((int)(*p - target) < 0) { }
    }
    __syncthreads();

    const int dh = d >> 1;   // u64 column index
    const u64* bsf = reinterpret_cast<const u64*>(g_sf) +
                     (size_t)b * kNChunk * kH * (kD / 2) + dh;
    const u64* bsr = reinterpret_cast<const u64*>(g_sr) +
                     (size_t)b * kNChunk * kH * (kD / 2) + dh;

    u64* od = reinterpret_cast<u64*>(
        out + ((size_t)b * kL + (size_t)c * kChunk) * kD + dt * kCols) + tid;

    // ================= phase 3a: forward (lookback prefix + rescan) ========
    {
        u64 u[kH];
        float wk[kH];
#pragma unroll
        for (int h = 0; h < kH; ++h) { u[h] = 0ull; wk[h] = 1.0f; }
        const float qmax = s_qcmax[0];
        float wm = 1.0f;
        for (int k = 0; k < c; ++k) {                  // windowed lookback
            const u64* row = bsf + (size_t)(c - 1 - k) * kH * (kD / 2);
#pragma unroll
            for (int h = 0; h < kH; ++h) {
                u64 sv = row[h * (kD / 2)];
                u[h] = fma2(pack2(wk[h], wk[h]), sv, u[h]);
                wk[h] *= s_qc[0][h];
            }
            wm *= qmax;
            if (wm < 1e-8f) break;                     // uniform per block
        }

        u64 q2[kH], w[kH];
#pragma unroll
        for (int h = 0; h < kH; ++h) {
            float q = s_q[0][h], a = s_a[0][h];
            q2[h] = pack2(q, q);
            float e0 = ex[h * kD + d], e1 = ex[h * kD + d + 1];
            float r0 = re[h * kD + d], r1 = re[h * kD + d + 1];
            w[h] = pack2(e0 * r0 * a, e1 * r1 * a);
        }
#pragma unroll
        for (int i = 0; i < kChunk; ++i) {
            u64 xv = xs[i * (kD / 2)];                 // L1 hit
            u64 fs = 0ull;
#pragma unroll
            for (int h = 0; h < kH; ++h) {
                u[h] = fma2(q2[h], u[h], xv);
                fs   = fma2(w[h], u[h], fs);
            }
            acc[i * kThreads + tid] = fs;              // smem, no global RMW
        }
    }

    // ================= phase 3b: reverse (lookback prefix + rescan) ========
    {
        u64 u[kH];
        float wk[kH];
#pragma unroll
        for (int h = 0; h < kH; ++h) { u[h] = 0ull; wk[h] = 1.0f; }
        const float qmax = s_qcmax[1];
        float wm = 1.0f;
        for (int k = 0; k < kNChunk - 1 - c; ++k) {    // successors
            const u64* row = bsr + (size_t)(c + 1 + k) * kH * (kD / 2);
#pragma unroll
            for (int h = 0; h < kH; ++h) {
                u64 sv = row[h * (kD / 2)];
                u[h] = fma2(pack2(wk[h], wk[h]), sv, u[h]);
                wk[h] *= s_qc[1][h];
            }
            wm *= qmax;
            if (wm < 1e-8f) break;
        }

        u64 q2[kH], w[kH];
#pragma unroll
        for (int h = 0; h < kH; ++h) {
            float q = s_q[1][h], a = s_a[1][h];
            q2[h] = pack2(q, q);
            float e0 = ex[(kH + h) * kD + d], e1 = ex[(kH + h) * kD + d + 1];
            float r0 = re[(kH + h) * kD + d], r1 = re[(kH + h) * kD + d + 1];
            w[h] = pack2(e0 * r0 * a, e1 * r1 * a);
        }
#pragma unroll
        for (int i = kChunk - 1; i >= 0; --i) {
            u64 xv = xs[i * (kD / 2)];                 // L1 hit
            u64 rs = 0ull;
#pragma unroll
            for (int h = 0; h < kH; ++h) {
                u[h] = fma2(q2[h], u[h], xv);
                rs   = fma2(w[h], u[h], rs);
            }
            store_cs(od + i * (kD / 2),
                     add2(acc[i * kThreads + tid], rs));  // out written once
        }
    }
}

// ---------------------------------------------------------------------------
extern "C" void kernel_launch(void* const* d_in, const int* in_sizes, int n_in,
                              void* d_out, int out_size)
{
    const float* x   = (const float*)d_in[0];
    const float* ex  = (const float*)d_in[1];
    const float* re  = (const float*)d_in[2];
    const float* al  = (const float*)d_in[3];
    const float* da  = (const float*)d_in[4];
    const float* ral = (const float*)d_in[5];
    const float* rda = (const float*)d_in[6];
    float* out = (float*)d_out;

    ema_fused<<<kBlocks, kThreads>>>(x, ex, re, al, da, ral, rda, out);
}